// round 17
// baseline (speedup 1.0000x reference)
#include <cuda_runtime.h>
#include <math.h>

#define NE   65536
#define DIM  512
#define DFF  2048
#define LN_EPS 1e-5f

typedef unsigned short u16;
typedef unsigned int   u32;

// ---------------- scratch (device globals; no allocations) ----------------
__device__ __align__(16) u16 g_q16[(size_t)NE * DIM];  // qs (fp16, from Q gemm epilogue)
__device__ __align__(16) u16 g_v16[(size_t)NE * DIM];  // vs (fp16, from KV gemm epilogue)
__device__ __align__(16) u16 g_aq[(size_t)NE * DIM];   // ln_qry, later attn_output
__device__ __align__(16) u16 g_as[(size_t)NE * DIM];   // ln_src, later y (ln2 out)
__device__ __align__(16) u16 g_ff[(size_t)NE * DFF];   // gelu output
// weights single fp16;  KV interleaved: col 2d = Wk[:,d], col 2d+1 = Wv[:,d]
#define OFF_Q 0
#define OFF_KV (512*512)
#define OFF_H (3*512*512)
#define OFF_1 (4*512*512)
#define OFF_2 (4*512*512 + 512*2048)
#define W_TOT (4*512*512 + 2*512*2048)
__device__ __align__(16) u16 g_w[W_TOT];
// [0,DIM)=diag_raw  [DIM,2DIM)=ksum_raw  [2DIM]=|qs|^2  [2DIM+1]=|ks|^2
__device__ __align__(16) float g_red[2 * DIM + 8];

// ---------------- fp16-as-bits helpers ----------------
__device__ __forceinline__ u16 f2h(float x) {
    u16 h;
    asm("cvt.rn.f16.f32 %0, %1;" : "=h"(h) : "f"(x));
    return h;
}
__device__ __forceinline__ float h2f(u16 h) {
    float f;
    asm("cvt.f32.f16 %0, %1;" : "=f"(f) : "h"(h));
    return f;
}
__device__ __forceinline__ u32 pack2(u16 a, u16 b) {
    return (u32)a | ((u32)b << 16);
}

__device__ __forceinline__ u32 smem_u32(const void* p) {
    return (u32)__cvta_generic_to_shared(p);
}
__device__ __forceinline__ void ldsm_x4(u32* r, u32 a) {
    asm volatile("ldmatrix.sync.aligned.m8n8.x4.shared.b16 {%0,%1,%2,%3}, [%4];"
                 : "=r"(r[0]), "=r"(r[1]), "=r"(r[2]), "=r"(r[3]) : "r"(a));
}
__device__ __forceinline__ void ldsm_x4t(u32* r, u32 a) {
    asm volatile("ldmatrix.sync.aligned.m8n8.x4.trans.shared.b16 {%0,%1,%2,%3}, [%4];"
                 : "=r"(r[0]), "=r"(r[1]), "=r"(r[2]), "=r"(r[3]) : "r"(a));
}
__device__ __forceinline__ void mma16816(float* d, const u32* a, const u32* b) {
    asm volatile("mma.sync.aligned.m16n8k16.row.col.f32.f16.f16.f32 "
                 "{%0,%1,%2,%3}, {%4,%5,%6,%7}, {%8,%9}, {%0,%1,%2,%3};"
                 : "+f"(d[0]), "+f"(d[1]), "+f"(d[2]), "+f"(d[3])
                 : "r"(a[0]), "r"(a[1]), "r"(a[2]), "r"(a[3]), "r"(b[0]), "r"(b[1]));
}
__device__ __forceinline__ void cpa16(u32 dst, const void* src) {
    asm volatile("cp.async.cg.shared.global [%0], [%1], 16;" :: "r"(dst), "l"(src));
}
__device__ __forceinline__ void cp_commit() {
    asm volatile("cp.async.commit_group;");
}
template <int N>
__device__ __forceinline__ void cp_wait() {
    asm volatile("cp.async.wait_group %0;" :: "n"(N));
}

// ---------------- small kernels ----------------
__global__ void zero_red_kernel() {
    int i = blockIdx.x * blockDim.x + threadIdx.x;
    if (i < 2 * DIM + 8) g_red[i] = 0.0f;
}

__global__ void wsplit_kernel(const float* __restrict__ src, int off, int n4) {
    int i = blockIdx.x * 256 + threadIdx.x;
    if (i < n4) {
        float4 v = ((const float4*)src)[i];
        size_t o = (size_t)off + (size_t)i * 4;
        *(u32*)(g_w + o)     = pack2(f2h(v.x), f2h(v.y));
        *(u32*)(g_w + o + 2) = pack2(f2h(v.z), f2h(v.w));
    }
}

// interleave Wk|Wv -> g_w[OFF_KV + k*1024 + 2d(+1)]
__global__ void wsplit_kv_kernel(const float* __restrict__ Wk, const float* __restrict__ Wv) {
    int i = blockIdx.x * 256 + threadIdx.x;   // over 512*512/4
    if (i < 512 * 512 / 4) {
        int k = i >> 7, dq = i & 127;         // d0 = dq*4
        float4 a = ((const float4*)(Wk + (size_t)k * 512))[dq];
        float4 b = ((const float4*)(Wv + (size_t)k * 512))[dq];
        size_t o = (size_t)OFF_KV + (size_t)k * 1024 + dq * 8;
        *(u32*)(g_w + o)     = pack2(f2h(a.x), f2h(b.x));
        *(u32*)(g_w + o + 2) = pack2(f2h(a.y), f2h(b.y));
        *(u32*)(g_w + o + 4) = pack2(f2h(a.z), f2h(b.z));
        *(u32*)(g_w + o + 6) = pack2(f2h(a.w), f2h(b.w));
    }
}

// layernorm -> single fp16.  DST: 0 -> g_aq, 1 -> g_as
template <int DST>
__global__ void ln_kernel(const float* __restrict__ x,
                          const float* __restrict__ gamma, const float* __restrict__ beta) {
    u16* y = (DST == 0) ? g_aq : g_as;
    int row = blockIdx.x;
    int t = threadIdx.x;
    const float4* xin = (const float4*)(x + (size_t)row * DIM);
    float4 v = xin[t];
    float s1 = v.x + v.y + v.z + v.w;
    float s2 = v.x*v.x + v.y*v.y + v.z*v.z + v.w*v.w;
    #pragma unroll
    for (int o = 16; o; o >>= 1) {
        s1 += __shfl_xor_sync(0xffffffffu, s1, o);
        s2 += __shfl_xor_sync(0xffffffffu, s2, o);
    }
    __shared__ float sh1[4], sh2[4];
    int w = t >> 5;
    if ((t & 31) == 0) { sh1[w] = s1; sh2[w] = s2; }
    __syncthreads();
    s1 = sh1[0] + sh1[1] + sh1[2] + sh1[3];
    s2 = sh2[0] + sh2[1] + sh2[2] + sh2[3];
    float mean = s1 * (1.0f / DIM);
    float var  = s2 * (1.0f / DIM) - mean * mean;
    float rstd = rsqrtf(var + LN_EPS);
    float4 gg = ((const float4*)gamma)[t];
    float4 bb = ((const float4*)beta)[t];
    float o0 = (v.x - mean) * rstd * gg.x + bb.x;
    float o1 = (v.y - mean) * rstd * gg.y + bb.y;
    float o2 = (v.z - mean) * rstd * gg.z + bb.z;
    float o3 = (v.w - mean) * rstd * gg.w + bb.w;
    size_t off = (size_t)row * DIM + t * 4;
    *(u32*)(y + off)     = pack2(f2h(o0), f2h(o1));
    *(u32*)(y + off + 2) = pack2(f2h(o2), f2h(o3));
}

// attention finalize: reads g_q16/g_v16 + g_red, writes fp16 attn_output to g_aq
__global__ void attn_kernel() {
    int row = blockIdx.x;
    int t = threadIdx.x;  // cols 4t..4t+3; head = t/16
    float rFq = rsqrtf(g_red[2 * DIM]);
    float rFk = rsqrtf(g_red[2 * DIM + 1]);
    const float nf = (float)NE;
    size_t base = (size_t)row * DIM;
    u32 qa = ((const u32*)(g_q16 + base))[2 * t];
    u32 qb = ((const u32*)(g_q16 + base))[2 * t + 1];
    u32 va = ((const u32*)(g_v16 + base))[2 * t];
    u32 vb = ((const u32*)(g_v16 + base))[2 * t + 1];
    float q0 = h2f((u16)(qa & 0xFFFF)), q1 = h2f((u16)(qa >> 16));
    float q2 = h2f((u16)(qb & 0xFFFF)), q3 = h2f((u16)(qb >> 16));
    float v0 = h2f((u16)(va & 0xFFFF)), v1 = h2f((u16)(va >> 16));
    float v2 = h2f((u16)(vb & 0xFFFF)), v3 = h2f((u16)(vb >> 16));
    float4 dg = ((const float4*)(g_red))[t];
    float4 km = ((const float4*)(g_red + DIM))[t];
    float p = (q0*km.x + q1*km.y + q2*km.z + q3*km.w) * (rFq * rFk);
    #pragma unroll
    for (int o = 8; o; o >>= 1) p += __shfl_xor_sync(0xffffffffu, p, o);
    float inv = 1.0f / (p + nf);
    float s = rFq * rFk;
    float o0 = (q0 * s * dg.x + v0 * nf) * inv;
    float o1 = (q1 * s * dg.y + v1 * nf) * inv;
    float o2 = (q2 * s * dg.z + v2 * nf) * inv;
    float o3 = (q3 * s * dg.w + v3 * nf) * inv;
    size_t off = base + t * 4;
    *(u32*)(g_aq + off)     = pack2(f2h(o0), f2h(o1));
    *(u32*)(g_aq + off + 2) = pack2(f2h(o2), f2h(o3));
}

// ---------------- single-fp16 tensor-core GEMM, K-slab 64, 3-stage cp.async ----------------
// ASEL: 0 -> g_aq, 1 -> g_as, 2 -> g_ff
// EPI 1: +bias+res -> Carg     EPI 2: gelu(+bias) -> g_ff(fp16)   EPI 3: +bias+res -> Carg
// EPI 4: Q  (+bias -> g_q16 fp16, accumulate |qs|^2)
// EPI 5: KV (interleaved cols; diag/ksum/|ks|^2, vs staged->coalesced fp16)
// Stage (bytes): A[128x64]@0 (16K, 128B rows, swizzle c^(r&7)),
//                B[64x128]@16384 (16K, 256B rows, chunk c^(r&7)).  32KB/stage.
// 2 CTAs/SM.
#define STG_BYTES 32768
#define SMEM_DYN (3 * STG_BYTES)
template <int EPI, int ASEL>
__global__ void __launch_bounds__(256, 2)
mma_gemm(int boff, const float* __restrict__ bias, const float* __restrict__ bias2,
         const float* __restrict__ res, float* __restrict__ Carg, int M, int N, int K)
{
    const u16* A = (ASEL == 0) ? g_aq : (ASEL == 1) ? g_as : g_ff;
    const u16* B = g_w + boff;

    extern __shared__ __align__(16) u16 smem[];
    const int tid = threadIdx.x, lane = tid & 31, warp = tid >> 5;
    const int wm = warp >> 1, wn = warp & 1;            // 4 x 2 warp grid, 32x64
    const int row0 = blockIdx.y * 128;
    const int col0 = blockIdx.x * 128;

    float acc[2][8][4];
    #pragma unroll
    for (int i = 0; i < 2; i++)
        #pragma unroll
        for (int j = 0; j < 8; j++)
            #pragma unroll
            for (int c = 0; c < 4; c++) acc[i][j][c] = 0.0f;

    const u32 sBase = smem_u32(smem);

    const int lrA = lane & 15, lgA = lane >> 4;
    const int lkB = (lane & 7) + ((lane >> 3) & 1) * 8;
    const int lgB = lane >> 4;
    // A fill: 2 threads/row, 4 chunks(16B) each; B fill: 4 threads/row, 4 chunks each
    const int ar = tid >> 1, ac = (tid & 1) * 4;
    const int br = tid >> 2, bc = (tid & 3) * 4;

    const int nk = K >> 6;  // K/64 slabs (8 or 32)

    auto load_stage = [&](int stage, int slab) {
        int k0 = slab << 6;
        u32 sb = sBase + stage * STG_BYTES;
        const u16* ap = A + (size_t)(row0 + ar) * K + k0;
        const u16* bp = B + (size_t)(k0 + br) * N + col0;
        #pragma unroll
        for (int j = 0; j < 4; j++) {
            int c = ac + j;
            cpa16(sb + (u32)(ar * 128 + 16 * (c ^ (ar & 7))), ap + c * 8);
        }
        #pragma unroll
        for (int j = 0; j < 4; j++) {
            int c = bc + j;
            cpa16(sb + 16384 + (u32)(br * 256 + 16 * (c ^ (br & 7))), bp + c * 8);
        }
        cp_commit();
    };

    load_stage(0, 0);
    load_stage(1, 1);

    int stage = 0;
    for (int it = 0; it < nk; it++) {
        if (it + 1 < nk) cp_wait<1>(); else cp_wait<0>();
        __syncthreads();

        const u32 stA = sBase + stage * STG_BYTES;
        const u32 stB = stA + 16384;
        #pragma unroll
        for (int ks = 0; ks < 64; ks += 16) {
            u32 ahf[2][4];
            #pragma unroll
            for (int i = 0; i < 2; i++) {
                int r = wm * 32 + i * 16 + lrA;
                int G = (ks >> 3) + lgA;
                u32 off = (u32)(r * 128 + 16 * (G ^ (r & 7)));
                ldsm_x4(ahf[i], stA + off);
            }
            int kB = ks + lkB;
            #pragma unroll
            for (int jp = 0; jp < 4; jp++) {
                int G = wn * 8 + jp * 2 + lgB;
                u32 off = (u32)(kB * 256 + 16 * (G ^ (kB & 7)));
                u32 bhf[4];
                ldsm_x4t(bhf, stB + off);
                #pragma unroll
                for (int i = 0; i < 2; i++) {
                    #pragma unroll
                    for (int jj = 0; jj < 2; jj++) {
                        mma16816(acc[i][jp * 2 + jj], ahf[i], bhf + 2 * jj);
                    }
                }
            }
        }
        if (it + 2 < nk) {
            int ns = stage + 2;
            if (ns >= 3) ns -= 3;
            load_stage(ns, it + 2);
        }
        stage = (stage == 2) ? 0 : stage + 1;
    }

    const int cg = lane >> 2, ct = lane & 3;

    if (EPI <= 3) {
        #pragma unroll
        for (int i = 0; i < 2; i++) {
            #pragma unroll
            for (int jn = 0; jn < 8; jn++) {
                int col = col0 + wn * 64 + jn * 8 + ct * 2;
                float b0 = bias[col], b1 = bias[col + 1];
                #pragma unroll
                for (int h = 0; h < 2; h++) {
                    int row = row0 + wm * 32 + i * 16 + cg + h * 8;
                    size_t idx = (size_t)row * N + col;
                    float v0 = acc[i][jn][h * 2 + 0] + b0;
                    float v1 = acc[i][jn][h * 2 + 1] + b1;
                    if (EPI == 1 || EPI == 3) {
                        float2 r2 = *(const float2*)(res + idx);
                        v0 += r2.x; v1 += r2.y;
                    }
                    if (EPI == 2) {
                        v0 = 0.5f * v0 * (1.0f + erff(v0 * 0.7071067811865476f));
                        v1 = 0.5f * v1 * (1.0f + erff(v1 * 0.7071067811865476f));
                        *(u32*)(g_ff + idx) = pack2(f2h(v0), f2h(v1));
                    } else {
                        *(float2*)(Carg + idx) = make_float2(v0, v1);
                    }
                }
            }
        }
    } else if (EPI == 4) {
        // Q: store fp16 + accumulate |qs|^2
        float sq2 = 0.0f;
        #pragma unroll
        for (int i = 0; i < 2; i++) {
            #pragma unroll
            for (int jn = 0; jn < 8; jn++) {
                int col = col0 + wn * 64 + jn * 8 + ct * 2;
                float b0 = bias[col], b1 = bias[col + 1];
                #pragma unroll
                for (int h = 0; h < 2; h++) {
                    int row = row0 + wm * 32 + i * 16 + cg + h * 8;
                    size_t idx = (size_t)row * N + col;
                    float v0 = acc[i][jn][h * 2 + 0] + b0;
                    float v1 = acc[i][jn][h * 2 + 1] + b1;
                    sq2 += v0 * v0 + v1 * v1;
                    *(u32*)(g_q16 + idx) = pack2(f2h(v0), f2h(v1));
                }
            }
        }
        #pragma unroll
        for (int o = 16; o; o >>= 1) sq2 += __shfl_xor_sync(0xffffffffu, sq2, o);
        if (lane == 0) atomicAdd(&g_red[2 * DIM], sq2);
    } else {
        // KV: interleaved cols (even=ks, odd=vs). vs staged in smem for coalesced writes.
        u16* vstage = smem;                              // [128][66] u16 (stage-0 region, free)
        float* sdS = (float*)(smem + 128 * 66);          // [64]
        float* skS = sdS + 64;                           // [64]
        __syncthreads();
        if (tid < 64) { sdS[tid] = 0.0f; skS[tid] = 0.0f; }
        __syncthreads();

        float sd_loc[8], sk_loc[8], sk2 = 0.0f;
        #pragma unroll
        for (int jn = 0; jn < 8; jn++) { sd_loc[jn] = 0.0f; sk_loc[jn] = 0.0f; }
        #pragma unroll
        for (int i = 0; i < 2; i++) {
            #pragma unroll
            for (int jn = 0; jn < 8; jn++) {
                int dloc = wn * 32 + jn * 4 + ct;
                int d = (col0 >> 1) + dloc;
                float bk_ = bias[d], bv_ = bias2[d];
                #pragma unroll
                for (int h = 0; h < 2; h++) {
                    int rloc = wm * 32 + i * 16 + cg + h * 8;
                    float ks = acc[i][jn][h * 2 + 0] + bk_;
                    float vs = acc[i][jn][h * 2 + 1] + bv_;
                    vstage[rloc * 66 + dloc] = f2h(vs);
                    sd_loc[jn] += ks * vs;
                    sk_loc[jn] += ks;
                    sk2 += ks * ks;
                }
            }
        }
        #pragma unroll
        for (int jn = 0; jn < 8; jn++) {
            #pragma unroll
            for (int o = 4; o < 32; o <<= 1) {
                sd_loc[jn] += __shfl_xor_sync(0xffffffffu, sd_loc[jn], o);
                sk_loc[jn] += __shfl_xor_sync(0xffffffffu, sk_loc[jn], o);
            }
        }
        if (lane < 4) {
            #pragma unroll
            for (int jn = 0; jn < 8; jn++) {
                int dl = wn * 32 + jn * 4 + lane;
                atomicAdd(&sdS[dl], sd_loc[jn]);
                atomicAdd(&skS[dl], sk_loc[jn]);
            }
        }
        #pragma unroll
        for (int o = 16; o; o >>= 1) sk2 += __shfl_xor_sync(0xffffffffu, sk2, o);
        if (lane == 0) atomicAdd(&g_red[2 * DIM + 1], sk2);
        __syncthreads();
        // coalesced vs write: 2 threads/row, 32 u16 (64B) each
        {
            int r = tid >> 1, hf = tid & 1;
            const u32* src = (const u32*)(vstage + r * 66 + hf * 32);
            u32* dst = (u32*)(g_v16 + (size_t)(row0 + r) * DIM + (col0 >> 1) + hf * 32);
            #pragma unroll
            for (int j = 0; j < 16; j++) dst[j] = src[j];
        }
        if (tid < 64) {
            int d = (col0 >> 1) + tid;
            atomicAdd(&g_red[d], sdS[tid]);
            atomicAdd(&g_red[DIM + d], skS[tid]);
        }
    }
}

// ---------------- launcher ----------------
extern "C" void kernel_launch(void* const* d_in, const int* in_sizes, int n_in,
                              void* d_out_v, int out_size) {
    const float* q_in = (const float*)d_in[0];
    const float* s_in = (const float*)d_in[1];
    const float* Wq = (const float*)d_in[2];  const float* bq = (const float*)d_in[3];
    const float* Wk = (const float*)d_in[4];  const float* bk = (const float*)d_in[5];
    const float* Wv = (const float*)d_in[6];  const float* bv = (const float*)d_in[7];
    const float* Wh = (const float*)d_in[8];  const float* bh = (const float*)d_in[9];
    const float* lnkg = (const float*)d_in[10]; const float* lnkb = (const float*)d_in[11];
    const float* lnqg = (const float*)d_in[12]; const float* lnqb = (const float*)d_in[13];
    const float* ln2g = (const float*)d_in[14]; const float* ln2b = (const float*)d_in[15];
    const float* W1 = (const float*)d_in[16]; const float* b1 = (const float*)d_in[17];
    const float* W2 = (const float*)d_in[18]; const float* b2 = (const float*)d_in[19];
    float* out = (float*)d_out_v;

    cudaFuncSetAttribute(mma_gemm<4,0>, cudaFuncAttributeMaxDynamicSharedMemorySize, SMEM_DYN);
    cudaFuncSetAttribute(mma_gemm<5,1>, cudaFuncAttributeMaxDynamicSharedMemorySize, SMEM_DYN);
    cudaFuncSetAttribute(mma_gemm<1,0>, cudaFuncAttributeMaxDynamicSharedMemorySize, SMEM_DYN);
    cudaFuncSetAttribute(mma_gemm<2,1>, cudaFuncAttributeMaxDynamicSharedMemorySize, SMEM_DYN);
    cudaFuncSetAttribute(mma_gemm<3,2>, cudaFuncAttributeMaxDynamicSharedMemorySize, SMEM_DYN);

    dim3 blk(256);
    dim3 gQ(DIM / 128, NE / 128);        // (4, 512)
    dim3 gKV(1024 / 128, NE / 128);      // (8, 512)

    // Launch order: slot #6 (ncu -s 5 -c 1) = KV GEMM (the big one).
    wsplit_kernel<<<(512*512/4 + 255)/256, 256>>>(Wq, OFF_Q, 512*512/4);        // 1
    zero_red_kernel<<<(2 * DIM + 8 + 127) / 128, 128>>>();                       // 2
    wsplit_kv_kernel<<<(512*512/4 + 255)/256, 256>>>(Wk, Wv);                    // 3
    ln_kernel<1><<<NE, 128>>>(s_in, lnkg, lnkb);                                 // 4: ln_src -> as
    ln_kernel<0><<<NE, 128>>>(q_in, lnqg, lnqb);                                 // 5: ln_qry -> aq
    mma_gemm<5, 1><<<gKV, blk, SMEM_DYN>>>(OFF_KV, bk, bv, nullptr, nullptr, NE, 1024, DIM);     // 6: KV
    mma_gemm<4, 0><<<gQ, blk, SMEM_DYN>>>(OFF_Q, bq, nullptr, nullptr, nullptr, NE, DIM, DIM);   // 7: Q
    wsplit_kernel<<<(512*512/4 + 255)/256, 256>>>(Wh, OFF_H, 512*512/4);
    wsplit_kernel<<<(512*2048/4 + 255)/256, 256>>>(W1, OFF_1, 512*2048/4);
    wsplit_kernel<<<(2048*512/4 + 255)/256, 256>>>(W2, OFF_2, 2048*512/4);

    attn_kernel<<<NE, 128>>>();                    // -> g_aq (fp16 attn_output)

    // h_pre_ffn = source + attn @ Wh + bh -> out
    mma_gemm<1, 0><<<gQ, blk, SMEM_DYN>>>(OFF_H, bh, nullptr, s_in, out, NE, DIM, DIM);
    // y = LN(out) -> as
    ln_kernel<1><<<NE, 128>>>(out, ln2g, ln2b);
    // ffn = gelu(y @ W1 + b1) -> g_ff (fp16)
    mma_gemm<2, 1><<<dim3(DFF / 128, NE / 128), blk, SMEM_DYN>>>(OFF_1, b1, nullptr, nullptr, nullptr, NE, DFF, DIM);
    // out = out + ffn @ W2 + b2
    mma_gemm<3, 2><<<gQ, blk, SMEM_DYN>>>(OFF_2, b2, nullptr, out, out, NE, DIM, DFF);
}